// round 3
// baseline (speedup 1.0000x reference)
#include <cuda_runtime.h>
#include <cuda_bf16.h>

// ShiftKernelMaker: per (b,c) 7x7 slice, emit one-hot (==max) mask.
// Input : float32 [128, 4096, 7, 7]  -> flat 524288 slices x 49 floats
// Output: float32 [524288, 1, 7, 7]  -> same flat layout
//
// Pure streaming kernel (~206 MB total). Strategy: stage 128 slices/block
// through shared memory with float4-coalesced global transactions; one
// thread per slice does the 49-wide max + mask in registers.

constexpr int KK = 49;                 // 7*7
constexpr int SLICES_PER_BLOCK = 128;  // one slice per thread
constexpr int THREADS = 128;
constexpr int FLOATS_PER_BLOCK = SLICES_PER_BLOCK * KK;   // 6272 floats
constexpr int VEC4_PER_BLOCK   = FLOATS_PER_BLOCK / 4;    // 1568 (6272 % 4 == 0)
constexpr int VEC4_ITERS       = (VEC4_PER_BLOCK + THREADS - 1) / THREADS;  // 13

__global__ __launch_bounds__(THREADS)
void shift_mask_kernel(const float* __restrict__ in, float* __restrict__ out,
                       int n_blocks) {
    __shared__ float sm[FLOATS_PER_BLOCK];

    for (int blk = blockIdx.x; blk < n_blocks; blk += gridDim.x) {
        const size_t base = (size_t)blk * FLOATS_PER_BLOCK;

        // ---- cooperative float4 load: global -> smem ----
        // base*4 bytes = 25088*blk : 16B aligned. Fixed trip count (13) so
        // ptxas fully unrolls and front-batches all LDG.128 (high MLP).
        const float4* __restrict__ in4 = reinterpret_cast<const float4*>(in + base);
        float4* sm4 = reinterpret_cast<float4*>(sm);
        #pragma unroll
        for (int it = 0; it < VEC4_ITERS; it++) {
            int i = it * THREADS + threadIdx.x;
            if (i < VEC4_PER_BLOCK) sm4[i] = in4[i];
        }
        __syncthreads();

        // ---- thread-per-slice: 49-wide max + mask in registers ----
        // smem index = tid*49 + i : 49 odd => per-i addresses form a lane
        // permutation mod 32 banks => conflict-free.
        {
            float v[KK];
            float* row = sm + threadIdx.x * KK;
            #pragma unroll
            for (int i = 0; i < KK; i++) v[i] = row[i];

            float mx = v[0];
            #pragma unroll
            for (int i = 1; i < KK; i++) mx = fmaxf(mx, v[i]);

            #pragma unroll
            for (int i = 0; i < KK; i++) row[i] = (v[i] == mx) ? 1.0f : 0.0f;
        }
        __syncthreads();

        // ---- cooperative float4 store: smem -> global ----
        float4* __restrict__ out4 = reinterpret_cast<float4*>(out + base);
        #pragma unroll
        for (int it = 0; it < VEC4_ITERS; it++) {
            int i = it * THREADS + threadIdx.x;
            if (i < VEC4_PER_BLOCK) out4[i] = sm4[i];
        }
        __syncthreads();  // protect smem reuse across grid-stride iterations
    }
}

extern "C" void kernel_launch(void* const* d_in, const int* in_sizes, int n_in,
                              void* d_out, int out_size) {
    const float* in = (const float*)d_in[0];
    float* out = (float*)d_out;

    const int n_elems  = in_sizes[0];                       // 25690112
    const int n_slices = n_elems / KK;                      // 524288
    const int n_blocks = n_slices / SLICES_PER_BLOCK;       // 4096 (exact)

    shift_mask_kernel<<<n_blocks, THREADS>>>(in, out, n_blocks);
}

// round 4
// speedup vs baseline: 1.1069x; 1.1069x over previous
#include <cuda_runtime.h>
#include <cuda_bf16.h>

// ShiftKernelMaker: per (b,c) 7x7 slice, emit one-hot (==max) mask.
// Input : float32 [128, 4096, 7, 7]  -> flat 524288 slices x 49 floats
// Output: float32 [524288, 1, 7, 7]  -> same flat layout
//
// R3 -> R4: kill register spills (no float v[49]) and the mask smem staging
// pass. Max phase keeps only a running max; copy-out re-reads the linear
// float4s and fuses the (v == max[slice]) compare with the coalesced STG.
// smem crossbar traffic/block: 125KB -> ~75KB; regs 64 -> ~32.

constexpr int KK = 49;                 // 7*7
constexpr int SLICES_PER_BLOCK = 128;  // one slice per thread
constexpr int THREADS = 128;
constexpr int FLOATS_PER_BLOCK = SLICES_PER_BLOCK * KK;   // 6272 floats
constexpr int VEC4_PER_BLOCK   = FLOATS_PER_BLOCK / 4;    // 1568 (6272 % 4 == 0)
constexpr int VEC4_ITERS       = (VEC4_PER_BLOCK + THREADS - 1) / THREADS;  // 13

__global__ __launch_bounds__(THREADS)
void shift_mask_kernel(const float* __restrict__ in, float* __restrict__ out,
                       int n_blocks) {
    __shared__ float sm[FLOATS_PER_BLOCK];
    __shared__ float smax[SLICES_PER_BLOCK];

    for (int blk = blockIdx.x; blk < n_blocks; blk += gridDim.x) {
        const size_t base = (size_t)blk * FLOATS_PER_BLOCK;

        // ---- phase 1: cooperative float4 load, global -> smem ----
        // base*4 bytes = 25088*blk : 16B aligned. Fixed trip count (13) so
        // ptxas fully unrolls and front-batches all LDG.128 (high MLP).
        const float4* __restrict__ in4 = reinterpret_cast<const float4*>(in + base);
        float4* sm4 = reinterpret_cast<float4*>(sm);
        #pragma unroll
        for (int it = 0; it < VEC4_ITERS; it++) {
            int i = it * THREADS + threadIdx.x;
            if (i < VEC4_PER_BLOCK) sm4[i] = in4[i];
        }
        __syncthreads();

        // ---- phase 2: running max of own row (49 scalar LDS, no array) ----
        // smem index = tid*49 + i : 49 odd => conflict-free lane permutation.
        {
            const float* row = sm + threadIdx.x * KK;
            float mx = row[0];
            #pragma unroll
            for (int i = 1; i < KK; i++) mx = fmaxf(mx, row[i]);
            smax[threadIdx.x] = mx;
        }
        __syncthreads();

        // ---- phase 3: fused mask + coalesced store ----
        // Re-read linear float4s; element at block-local float offset f
        // belongs to slice f/49. A float4 spans at most 2 adjacent slices:
        // look up both maxes, select per element via the slice boundary.
        float4* __restrict__ out4 = reinterpret_cast<float4*>(out + base);
        #pragma unroll
        for (int it = 0; it < VEC4_ITERS; it++) {
            int i = it * THREADS + threadIdx.x;
            if (i < VEC4_PER_BLOCK) {
                float4 v = sm4[i];
                unsigned f = 4u * (unsigned)i;
                unsigned s0 = f / 49u;            // exact magic-mul (ALU pipe)
                unsigned s3 = (f + 3u) / 49u;
                float m0 = smax[s0];
                float m3 = smax[s3];              // == m0 when no boundary
                unsigned boundary = (s0 + 1u) * 49u;
                float4 r;
                r.x = (v.x == ((f + 0u < boundary) ? m0 : m3)) ? 1.0f : 0.0f;
                r.y = (v.y == ((f + 1u < boundary) ? m0 : m3)) ? 1.0f : 0.0f;
                r.z = (v.z == ((f + 2u < boundary) ? m0 : m3)) ? 1.0f : 0.0f;
                r.w = (v.w == ((f + 3u < boundary) ? m0 : m3)) ? 1.0f : 0.0f;
                out4[i] = r;
            }
        }
        __syncthreads();  // protect smem reuse across grid-stride iterations
    }
}

extern "C" void kernel_launch(void* const* d_in, const int* in_sizes, int n_in,
                              void* d_out, int out_size) {
    const float* in = (const float*)d_in[0];
    float* out = (float*)d_out;

    const int n_elems  = in_sizes[0];                       // 25690112
    const int n_slices = n_elems / KK;                      // 524288
    const int n_blocks = n_slices / SLICES_PER_BLOCK;       // 4096 (exact)

    shift_mask_kernel<<<n_blocks, THREADS>>>(in, out, n_blocks);
}

// round 5
// speedup vs baseline: 1.1426x; 1.0323x over previous
#include <cuda_runtime.h>
#include <cuda_bf16.h>

// ShiftKernelMaker: per (b,c) 7x7 slice, emit one-hot (==max) mask.
// Input : float32 [128, 4096, 7, 7]  -> flat 524288 slices x 49 floats
// Output: float32 [524288, 1, 7, 7]  -> same flat layout
//
// R4 -> R5: drop shared memory entirely. Warp-per-slice: lane l holds x[l]
// and (l<17) x[l+32]; warp max via 5 shfl.bfly; mask stored with 2 coalesced
// STG per slice. Each warp batches 4 slices for MLP=8 LDGs in flight.
// No barriers, no LDS/STS, no integer division. regs ~28 -> 100% occupancy.

constexpr int KK = 49;                // 7*7
constexpr int THREADS = 256;
constexpr int WARPS_PER_BLOCK = THREADS / 32;       // 8
constexpr int SLICES_PER_WARP = 4;
constexpr int SLICES_PER_BLOCK = WARPS_PER_BLOCK * SLICES_PER_WARP;  // 32

__global__ __launch_bounds__(THREADS, 8)
void shift_mask_kernel(const float* __restrict__ in, float* __restrict__ out,
                       int n_slices) {
    const int warp = threadIdx.x >> 5;
    const int lane = threadIdx.x & 31;
    const int slice0 = (blockIdx.x * WARPS_PER_BLOCK + warp) * SLICES_PER_WARP;

    if (slice0 + SLICES_PER_WARP <= n_slices) {
        // ---- fast path: 4 full slices, all loads front-batched ----
        const float* __restrict__ p = in + (size_t)slice0 * KK;
        float a[SLICES_PER_WARP], b[SLICES_PER_WARP];
        #pragma unroll
        for (int s = 0; s < SLICES_PER_WARP; s++) {
            a[s] = p[s * KK + lane];                               // elems 0..31
            b[s] = (lane < KK - 32) ? p[s * KK + 32 + lane] : a[s]; // elems 32..48
        }

        float m[SLICES_PER_WARP];
        #pragma unroll
        for (int s = 0; s < SLICES_PER_WARP; s++) {
            float mx = fmaxf(a[s], b[s]);
            #pragma unroll
            for (int off = 16; off; off >>= 1)
                mx = fmaxf(mx, __shfl_xor_sync(0xffffffffu, mx, off));
            m[s] = mx;
        }

        float* __restrict__ q = out + (size_t)slice0 * KK;
        #pragma unroll
        for (int s = 0; s < SLICES_PER_WARP; s++) {
            q[s * KK + lane] = (a[s] == m[s]) ? 1.0f : 0.0f;
            if (lane < KK - 32)
                q[s * KK + 32 + lane] = (b[s] == m[s]) ? 1.0f : 0.0f;
        }
    } else {
        // ---- tail path (not taken for the benchmark shape) ----
        for (int s = 0; s < SLICES_PER_WARP; s++) {
            int slice = slice0 + s;
            if (slice >= n_slices) break;
            const float* p = in + (size_t)slice * KK;
            float a = p[lane];
            float b = (lane < KK - 32) ? p[32 + lane] : a;
            float mx = fmaxf(a, b);
            #pragma unroll
            for (int off = 16; off; off >>= 1)
                mx = fmaxf(mx, __shfl_xor_sync(0xffffffffu, mx, off));
            float* q = out + (size_t)slice * KK;
            q[lane] = (a == mx) ? 1.0f : 0.0f;
            if (lane < KK - 32) q[32 + lane] = (b == mx) ? 1.0f : 0.0f;
        }
    }
}

extern "C" void kernel_launch(void* const* d_in, const int* in_sizes, int n_in,
                              void* d_out, int out_size) {
    const float* in = (const float*)d_in[0];
    float* out = (float*)d_out;

    const int n_elems  = in_sizes[0];                  // 25690112
    const int n_slices = n_elems / KK;                 // 524288
    const int grid = (n_slices + SLICES_PER_BLOCK - 1) / SLICES_PER_BLOCK; // 16384

    shift_mask_kernel<<<grid, THREADS>>>(in, out, n_slices);
}

// round 6
// speedup vs baseline: 1.1684x; 1.0226x over previous
#include <cuda_runtime.h>
#include <cuda_bf16.h>
#include <cstdint>

// ShiftKernelMaker: per (b,c) 7x7 slice, emit one-hot (==max) mask.
// Input : float32 [128, 4096, 7, 7]  -> flat 524288 slices x 49 floats
// Output: float32 [524288, 1, 7, 7]  -> same flat layout
//
// R5 -> R6: both prior designs capped at DRAM=57.4% because l1tex wavefront
// throughput was the binding constraint (unaligned LDG/STG or smem staging,
// 2.3-2.8x the necessary wavefronts). Fix: move ALL global traffic onto the
// TMA pipe (cp.async.bulk 1D, no tensormap), compute the mask IN PLACE in
// smem with conflict-free scalar LDS/STS (49 odd => lane permutation across
// banks). l1tex now carries only ~75KB/tile of smem scalars; HBM stream is
// TMA-driven. Blocks overlap each other's load/compute/store phases.

constexpr int KK = 49;                 // 7*7
constexpr int SLICES_PER_BLOCK = 128;  // one slice per thread
constexpr int THREADS = 128;
constexpr int TILE_FLOATS = SLICES_PER_BLOCK * KK;   // 6272
constexpr int TILE_BYTES  = TILE_FLOATS * 4;         // 25088 (16B multiple)

__device__ __forceinline__ uint32_t smem_u32(const void* p) {
    uint32_t a;
    asm("{ .reg .u64 t; cvta.to.shared.u64 t, %1; cvt.u32.u64 %0, t; }"
        : "=r"(a) : "l"(p));
    return a;
}

__global__ __launch_bounds__(THREADS)
void shift_mask_kernel(const float* __restrict__ in, float* __restrict__ out) {
    __shared__ alignas(16) float tile[TILE_FLOATS];
    __shared__ alignas(8)  uint64_t mbar;

    const size_t base = (size_t)blockIdx.x * TILE_FLOATS;
    const uint32_t s_tile = smem_u32(tile);
    const uint32_t s_mbar = smem_u32(&mbar);

    // ---- TMA bulk load: global -> smem (single issuing thread) ----
    if (threadIdx.x == 0) {
        asm volatile("mbarrier.init.shared.b64 [%0], 1;" :: "r"(s_mbar) : "memory");
    }
    __syncthreads();
    if (threadIdx.x == 0) {
        asm volatile("mbarrier.arrive.expect_tx.shared.b64 _, [%0], %1;"
                     :: "r"(s_mbar), "r"(TILE_BYTES) : "memory");
        asm volatile("cp.async.bulk.shared::cluster.global.mbarrier::complete_tx::bytes"
                     " [%0], [%1], %2, [%3];"
                     :: "r"(s_tile), "l"(in + base), "r"(TILE_BYTES), "r"(s_mbar)
                     : "memory");
    }

    // ---- wait for TMA completion (parity 0, acquire) ----
    {
        uint32_t done;
        asm volatile(
            "{\n\t"
            ".reg .pred p;\n\t"
            "mbarrier.try_wait.parity.acquire.cta.shared::cta.b64 p, [%1], 0;\n\t"
            "selp.b32 %0, 1, 0, p;\n\t"
            "}" : "=r"(done) : "r"(s_mbar) : "memory");
        if (!done) {
            asm volatile(
                "{\n\t"
                ".reg .pred P1;\n\t"
                "WAIT_LOOP_%=:\n\t"
                "mbarrier.try_wait.parity.acquire.cta.shared::cta.b64 P1, [%0], 0, 0x989680;\n\t"
                "@P1 bra.uni WAIT_DONE_%=;\n\t"
                "bra.uni WAIT_LOOP_%=;\n\t"
                "WAIT_DONE_%=:\n\t"
                "}" :: "r"(s_mbar) : "memory");
        }
    }

    // ---- compute: per-thread row max, then in-place mask ----
    // smem index = tid*49 + i : 49 odd => conflict-free bank permutation.
    {
        float* row = tile + threadIdx.x * KK;
        float mx = row[0];
        #pragma unroll
        for (int i = 1; i < KK; i++) mx = fmaxf(mx, row[i]);
        #pragma unroll
        for (int i = 0; i < KK; i++) row[i] = (row[i] == mx) ? 1.0f : 0.0f;
    }
    __syncthreads();

    // ---- TMA bulk store: smem -> global ----
    asm volatile("fence.proxy.async.shared::cta;" ::: "memory");
    if (threadIdx.x == 0) {
        asm volatile("cp.async.bulk.global.shared::cta.bulk_group [%0], [%1], %2;"
                     :: "l"(out + base), "r"(s_tile), "r"(TILE_BYTES) : "memory");
        asm volatile("cp.async.bulk.commit_group;" ::: "memory");
        asm volatile("cp.async.bulk.wait_group.read 0;" ::: "memory");
    }
}

extern "C" void kernel_launch(void* const* d_in, const int* in_sizes, int n_in,
                              void* d_out, int out_size) {
    const float* in = (const float*)d_in[0];
    float* out = (float*)d_out;

    const int n_elems  = in_sizes[0];                    // 25690112
    const int n_slices = n_elems / KK;                   // 524288
    const int grid     = n_slices / SLICES_PER_BLOCK;    // 4096 (exact)

    shift_mask_kernel<<<grid, THREADS>>>(in, out);
}